// round 15
// baseline (speedup 1.0000x reference)
#include <cuda_runtime.h>

// 9x9 zero-padded box filter, 128 independent 512x512 fp32 images.
// Full-width row pipeline (champion geometry: 512-wide x 64-row band).
// Single-global-read variant: a running column prefix sum
// Q(y) = sum rows [y0-5..y] lives in registers; a private 10-slot smem
// ring holds Q history so the old row x[y-5] is never re-read from
// global: vsum(y) = Q(y+4) - Q(y-5). Each thread touches only its own
// ring column (no barrier needed for the Q ring). Horizontal 9-sum via
// the usual vsum smem ring + 2 neighbor LDS; streaming output stores.
// R15: fixed ring cursor (R14's slot arithmetic indexed out of bounds).

#define W   512
#define H   512
#define TH  64                  // rows per CTA band
#define NT  128                 // one thread per float4 column group
#define W4  (W / 4)             // 128

__global__ __launch_bounds__(NT) void box9_kernel(const float* __restrict__ xin,
                                                  float* __restrict__ outp) {
    // hsum exchange ring: 4 row-slots, zero halo at 0 and 129.
    __shared__ __align__(16) float4 buf[4][132];
    // Q history ring: slot j holds Q for one row; own column only.
    __shared__ __align__(16) float4 qring[10][W4];

    const int t  = threadIdx.x;
    const int y0 = blockIdx.x * TH;
    const size_t imgoff = (size_t)blockIdx.y * (W * H);
    const float4* __restrict__ base  = reinterpret_cast<const float4*>(xin + imgoff);
    float4* __restrict__       obase = reinterpret_cast<float4*>(outp + imgoff);

    const float4 z4 = make_float4(0.f, 0.f, 0.f, 0.f);
    if (t < 4) {
        buf[t][0]   = z4;
        buf[t][129] = z4;
    }

    // ---- prologue: build Q(r) for r = y0-5 .. y0+3 into slots 0..8 ----
    float4 Q = z4;
    #pragma unroll
    for (int j = 0; j < 9; j++) {
        int r = y0 - 5 + j;
        if ((unsigned)r < (unsigned)H) {
            float4 v = base[r * W4 + t];
            Q.x += v.x; Q.y += v.y; Q.z += v.z; Q.w += v.w;
        }
        qring[j][t] = Q;
    }

    // prefetch new rows for the first iteration: n = x[y+4], y = y0, y0+1
    float4 n0 = z4, n1 = z4;
    { int r;
      r = y0 + 4; if ((unsigned)r < (unsigned)H) n0 = base[r * W4 + t];
      r = y0 + 5; if ((unsigned)r < (unsigned)H) n1 = base[r * W4 + t];
    }

    // ring cursor: slot rp holds Q(y-5) for the current output row y.
    int rp = 0;

    #pragma unroll 2
    for (int k = 0; k < TH / 2; k++) {
        const int y   = y0 + 2 * k;
        const int idx = 2 * k;               // y - y0
        float4 na = n0, nb = n1;

        // prefetch new rows for next iteration (y+2, y+3)
        if (k + 1 < TH / 2) {
            int r;
            n0 = z4; n1 = z4;
            r = y + 6; if ((unsigned)r < (unsigned)H) n0 = base[r * W4 + t];
            r = y + 7; if ((unsigned)r < (unsigned)H) n1 = base[r * W4 + t];
        }

        // ---- row y: Q(y+4) = Q + n; vs = Q(y+4) - Q(y-5) ----
        Q.x += na.x; Q.y += na.y; Q.z += na.z; Q.w += na.w;
        {
            int wp = rp + 9; if (wp >= 10) wp -= 10;   // rp<10 -> wp<19, one wrap ok
            qring[wp][t] = Q;
        }
        float4 qo0 = qring[rp][t];
        rp += 1; if (rp >= 10) rp -= 10;
        float4 vs0 = make_float4(Q.x - qo0.x, Q.y - qo0.y,
                                 Q.z - qo0.z, Q.w - qo0.w);
        buf[idx & 3][t + 1] = vs0;

        // ---- row y+1 ----
        Q.x += nb.x; Q.y += nb.y; Q.z += nb.z; Q.w += nb.w;
        {
            int wp = rp + 9; if (wp >= 10) wp -= 10;
            qring[wp][t] = Q;
        }
        float4 qo1 = qring[rp][t];
        rp += 1; if (rp >= 10) rp -= 10;
        float4 vs1 = make_float4(Q.x - qo1.x, Q.y - qo1.y,
                                 Q.z - qo1.z, Q.w - qo1.w);
        buf[(idx + 1) & 3][t + 1] = vs1;

        __syncthreads();

        // horizontal slide, row y (streaming store)
        {
            float4 a = buf[idx & 3][t];
            float4 c = buf[idx & 3][t + 2];
            float sb = (vs0.x + vs0.y) + (vs0.z + vs0.w);
            float sa = (a.x + a.y) + (a.z + a.w);
            float h0 = sa + sb + c.x;
            float h1 = h0 - a.x + c.y;
            float h2 = h1 - a.y + c.z;
            float h3 = h2 - a.z + c.w;
            __stcs(&obase[y * W4 + t], make_float4(h0, h1, h2, h3));
        }
        // horizontal slide, row y+1
        {
            float4 a = buf[(idx + 1) & 3][t];
            float4 c = buf[(idx + 1) & 3][t + 2];
            float sb = (vs1.x + vs1.y) + (vs1.z + vs1.w);
            float sa = (a.x + a.y) + (a.z + a.w);
            float h0 = sa + sb + c.x;
            float h1 = h0 - a.x + c.y;
            float h2 = h1 - a.y + c.z;
            float h3 = h2 - a.z + c.w;
            __stcs(&obase[(y + 1) * W4 + t], make_float4(h0, h1, h2, h3));
        }
    }
}

extern "C" void kernel_launch(void* const* d_in, const int* in_sizes, int n_in,
                              void* d_out, int out_size) {
    const float* x = (const float*)d_in[0];
    float* out = (float*)d_out;
    int nimg = in_sizes[0] / (W * H);     // 128
    dim3 grid(H / TH, nimg);              // (8, 128) = 1024 CTAs
    box9_kernel<<<grid, NT>>>(x, out);
}

// round 16
// speedup vs baseline: 1.0842x; 1.0842x over previous
#include <cuda_runtime.h>

// 9x9 zero-padded box filter, 128 independent 512x512 fp32 images.
// FINAL (champion): full-width row pipeline, CTA = 512-wide x 64-row band.
// Vertical 9-sum slides in registers (new row from DRAM, old row from L1/L2),
// horizontal 9-sum via one smem float4 store + 2 neighbor float4 loads,
// streaming (__stcs) output stores to preserve L2 input residency.
//
// Measured: ~41.9us kernel, 5.7 TB/s, ~238 MB DRAM traffic (at the in+out
// floor). Twelve structural perturbations (occupancy 28-45%, MLP depth,
// barrier topology, warp autonomy, width splits, cache policies, predicate
// specialization, prefix-sum re-read elimination) all landed within -5% or
// regressed: this access mix is at the chip's mixed-stream HBM ceiling.

#define W   512
#define H   512
#define TH  64                  // rows per CTA band
#define NT  128                 // one thread per float4 column group (512/4)
#define W4  (W / 4)             // 128

__global__ __launch_bounds__(NT) void box9_kernel(const float* __restrict__ xin,
                                                  float* __restrict__ outp) {
    // 4 row-buffers (2 rows in flight per barrier, alternating pairs).
    // Slot s: index t+1 is own column group; 0 and 129 are the zero halo.
    __shared__ __align__(16) float4 buf[4][132];

    const int t  = threadIdx.x;
    const int y0 = blockIdx.x * TH;
    const size_t imgoff = (size_t)blockIdx.y * (W * H);
    const float4* __restrict__ base  = reinterpret_cast<const float4*>(xin + imgoff);
    float4* __restrict__       obase = reinterpret_cast<float4*>(outp + imgoff);

    const float4 z4 = make_float4(0.f, 0.f, 0.f, 0.f);
    if (t < 4) {
        buf[t][0]   = z4;
        buf[t][129] = z4;
    }

    // ---- prologue: vs = sum of input rows [y0-5, y0+3] (zeros outside) ----
    // Invariant before the slide at output row y: vs = sum rows [y-5, y+3].
    float4 vs = z4;
    #pragma unroll
    for (int i = -5; i <= 3; i++) {
        int r = y0 + i;
        if ((unsigned)r < (unsigned)H) {
            float4 v = base[r * W4 + t];
            vs.x += v.x; vs.y += v.y; vs.z += v.z; vs.w += v.w;
        }
    }

    // prefetch rows for the first iteration (output rows y0, y0+1):
    //   n = x[y+4], o = x[y-5]
    float4 n0 = z4, o0 = z4, n1 = z4, o1 = z4;
    { int r;
      r = y0 + 4; if ((unsigned)r < (unsigned)H) n0 = base[r * W4 + t];
      r = y0 - 5; if ((unsigned)r < (unsigned)H) o0 = base[r * W4 + t];
      r = y0 + 5; if ((unsigned)r < (unsigned)H) n1 = base[r * W4 + t];
      r = y0 - 4; if ((unsigned)r < (unsigned)H) o1 = base[r * W4 + t];
    }

    #pragma unroll 2
    for (int k = 0; k < TH / 2; k++) {
        const int y = y0 + 2 * k;
        float4 na = n0, oa = o0, nb = n1, ob = o1;

        // prefetch rows for next iteration (output rows y+2, y+3)
        if (k + 1 < TH / 2) {
            int r;
            n0 = z4; o0 = z4; n1 = z4; o1 = z4;
            r = y + 6; if ((unsigned)r < (unsigned)H) n0 = base[r * W4 + t];
            r = y - 3; if ((unsigned)r < (unsigned)H) o0 = base[r * W4 + t];
            r = y + 7; if ((unsigned)r < (unsigned)H) n1 = base[r * W4 + t];
            r = y - 2; if ((unsigned)r < (unsigned)H) o1 = base[r * W4 + t];
        }

        // vertical slide, two rows
        vs.x += na.x - oa.x; vs.y += na.y - oa.y;
        vs.z += na.z - oa.z; vs.w += na.w - oa.w;
        float4 vs0 = vs;
        buf[(2 * k) & 3][t + 1] = vs0;

        vs.x += nb.x - ob.x; vs.y += nb.y - ob.y;
        vs.z += nb.z - ob.z; vs.w += nb.w - ob.w;
        float4 vs1 = vs;
        buf[(2 * k + 1) & 3][t + 1] = vs1;

        __syncthreads();

        // horizontal slide, row y (streaming store: keep L2 for input)
        {
            float4 a = buf[(2 * k) & 3][t];
            float4 c = buf[(2 * k) & 3][t + 2];
            float sb = (vs0.x + vs0.y) + (vs0.z + vs0.w);
            float sa = (a.x + a.y) + (a.z + a.w);
            float h0 = sa + sb + c.x;
            float h1 = h0 - a.x + c.y;
            float h2 = h1 - a.y + c.z;
            float h3 = h2 - a.z + c.w;
            __stcs(&obase[y * W4 + t], make_float4(h0, h1, h2, h3));
        }
        // horizontal slide, row y+1
        {
            float4 a = buf[(2 * k + 1) & 3][t];
            float4 c = buf[(2 * k + 1) & 3][t + 2];
            float sb = (vs1.x + vs1.y) + (vs1.z + vs1.w);
            float sa = (a.x + a.y) + (a.z + a.w);
            float h0 = sa + sb + c.x;
            float h1 = h0 - a.x + c.y;
            float h2 = h1 - a.y + c.z;
            float h3 = h2 - a.z + c.w;
            __stcs(&obase[(y + 1) * W4 + t], make_float4(h0, h1, h2, h3));
        }
    }
}

extern "C" void kernel_launch(void* const* d_in, const int* in_sizes, int n_in,
                              void* d_out, int out_size) {
    const float* x = (const float*)d_in[0];
    float* out = (float*)d_out;
    int nimg = in_sizes[0] / (W * H);     // 128
    dim3 grid(H / TH, nimg);              // (8, 128) = 1024 CTAs
    box9_kernel<<<grid, NT>>>(x, out);
}